// round 3
// baseline (speedup 1.0000x reference)
#include <cuda_runtime.h>
#include <stdint.h>

// FP32 bit-pulse -> FP8 E4M3 bit-pulse converter.
// Input:  N*32 floats, each 0.0/1.0, per value [S, E7..E0, M22..M0] (MSB first)
// Output: N*8  floats, per value [S, E3..E0, M2..M0]
//
// Lane l ballots bit-position l; __brev(ballot) reconstructs the IEEE fp32 word.
// Round-3 change: each warp processes TWO independent 32-value tiles. Tile B's
// loads stay outstanding while tile A's ballot/convert phase runs (ptxas cannot
// serialize them onto each other), removing the memory-demand bubble that the
// single-tile version has during its compute phase.

__device__ __forceinline__ void convert_and_store(uint32_t word, float* __restrict__ op)
{
    const uint32_t s    = word >> 31;
    const uint32_t exp  = (word >> 23) & 0xFFu;
    const uint32_t mant = word & 0x7FFFFFu;

    // ---- normal path: fp8_exp = exp - 120, RNE round 23 -> 3 mantissa bits ----
    uint32_t kept  = mant >> 20;
    uint32_t R     = (mant >> 19) & 1u;
    uint32_t S     = (mant & 0x7FFFFu) ? 1u : 0u;
    uint32_t L     = kept & 1u;
    uint32_t mr    = kept + (R & (S | L));
    uint32_t carry = mr >> 3;
    uint32_t mant_norm = carry ? 0u : (mr & 7u);
    int exp_norm = (int)exp - 120 + (int)carry;

    // ---- subnormal path (117 <= exp <= 120): shift 1.mant right, RNE ----
    uint32_t full = (1u << 23) | mant;
    int sh = 141 - (int)exp;
    sh = sh < 1 ? 1 : (sh > 24 ? 24 : sh);
    uint32_t kept_s = full >> sh;
    uint32_t Rs = (full >> (sh - 1)) & 1u;
    uint32_t Ss = (full & ((1u << (sh - 1)) - 1u)) ? 1u : 0u;
    uint32_t Ls = kept_s & 1u;
    uint32_t ms = kept_s + (Rs & (Ss | Ls));
    uint32_t sub_exp  = (ms >= 8u) ? 1u : 0u;
    uint32_t sub_mant = (ms >= 8u) ? 0u : ms;

    // ---- select overflow / subnormal / underflow / normal ----
    uint32_t exp8, mant8;
    if (exp > 134u) {
        exp8 = 15u; mant8 = 6u;
    } else if (exp >= 117u) {
        if (exp <= 120u) { exp8 = sub_exp; mant8 = sub_mant; }
        else             { exp8 = (uint32_t)exp_norm; mant8 = mant_norm; }
    } else {
        exp8 = 0u; mant8 = 0u;         // underflow
    }

    float4 o0 = make_float4((float)s,
                            (float)((exp8 >> 3) & 1u),
                            (float)((exp8 >> 2) & 1u),
                            (float)((exp8 >> 1) & 1u));
    float4 o1 = make_float4((float)(exp8 & 1u),
                            (float)((mant8 >> 2) & 1u),
                            (float)((mant8 >> 1) & 1u),
                            (float)(mant8 & 1u));

    float4* o = reinterpret_cast<float4*>(op);
    o[0] = o0;
    o[1] = o1;
}

__global__ void __launch_bounds__(256)
fp32_to_fp8_pulse_kernel(const float* __restrict__ in,
                         float* __restrict__ out,
                         int nvals)
{
    const int lane    = threadIdx.x & 31;
    const int warp_id = (blockIdx.x * blockDim.x + threadIdx.x) >> 5;
    const int base    = warp_id * 64;           // two 32-value tiles per warp
    if (base >= nvals) return;

    const float* pA = in + (size_t)base * 32;
    const float* pB = pA + 32 * 32;

    // Two independent load streams — tile B's loads remain in flight while
    // tile A's ballots consume tile A's loads.
    float fA[32], fB[32];
#pragma unroll
    for (int i = 0; i < 32; i++) fA[i] = pA[i * 32 + lane];
#pragma unroll
    for (int i = 0; i < 32; i++) fB[i] = pB[i * 32 + lane];

    uint32_t wA = 0, wB = 0;
#pragma unroll
    for (int i = 0; i < 32; i++) {
        uint32_t b = __ballot_sync(0xFFFFFFFFu, fA[i] > 0.5f);
        if (lane == i) wA = b;
    }
#pragma unroll
    for (int i = 0; i < 32; i++) {
        uint32_t b = __ballot_sync(0xFFFFFFFFu, fB[i] > 0.5f);
        if (lane == i) wB = b;
    }
    wA = __brev(wA);
    wB = __brev(wB);

    convert_and_store(wA, out + (size_t)(base + lane) * 8);
    convert_and_store(wB, out + (size_t)(base + 32 + lane) * 8);
}

extern "C" void kernel_launch(void* const* d_in, const int* in_sizes, int n_in,
                              void* d_out, int out_size)
{
    const float* in  = (const float*)d_in[0];
    float*       out = (float*)d_out;
    const int nvals  = in_sizes[0] / 32;       // 2,097,152

    const int threads = 256;                   // 8 warps * 64 values = 512 values/block
    const int values_per_block = (threads / 32) * 64;
    const int blocks = (nvals + values_per_block - 1) / values_per_block;

    fp32_to_fp8_pulse_kernel<<<blocks, threads>>>(in, out, nvals);
}

// round 4
// speedup vs baseline: 1.1393x; 1.1393x over previous
#include <cuda_runtime.h>
#include <stdint.h>

// FP32 bit-pulse -> FP8 E4M3 bit-pulse converter.
// Input:  N*32 floats, each 0.0/1.0, per value [S, E7..E0, M22..M0] (MSB first)
// Output: N*8  floats, per value [S, E3..E0, M2..M0]
//
// Lane l of the warp loads float (v*32 + l); __brev(__ballot(f > 0.5)) is
// exactly the IEEE-754 fp32 bit pattern of value v (S@31, E@30..23, M@22..0).
// Round-4: round-1 structure (best so far) + streaming cache hints:
// __ldcs on the gather (evict-first reads) and __stcs on the stores, keeping
// the zero-reuse read and write streams from thrashing L2 ways against each
// other.

__global__ void __launch_bounds__(256)
fp32_to_fp8_pulse_kernel(const float* __restrict__ in,
                         float* __restrict__ out,
                         int nvals)
{
    const int lane    = threadIdx.x & 31;
    const int warp_id = (blockIdx.x * blockDim.x + threadIdx.x) >> 5;
    const int base    = warp_id * 32;           // 32 values per warp
    if (base >= nvals) return;

    const float* p = in + (size_t)base * 32;

    // Gather + ballot: iteration i reconstructs value (base + i); lane i keeps it.
    uint32_t word = 0;
#pragma unroll
    for (int i = 0; i < 32; i++) {
        float f = __ldcs(&p[i * 32 + lane]);    // streaming load, evict-first
        uint32_t b = __ballot_sync(0xFFFFFFFFu, f > 0.5f);
        if (lane == i) word = b;
    }
    word = __brev(word);   // standard IEEE fp32 bit pattern

    const uint32_t s    = word >> 31;
    const uint32_t exp  = (word >> 23) & 0xFFu;
    const uint32_t mant = word & 0x7FFFFFu;

    // ---- normal path: fp8_exp = exp - 120, RNE round 23 -> 3 mantissa bits ----
    uint32_t kept  = mant >> 20;
    uint32_t R     = (mant >> 19) & 1u;
    uint32_t S     = (mant & 0x7FFFFu) ? 1u : 0u;
    uint32_t L     = kept & 1u;
    uint32_t mr    = kept + (R & (S | L));
    uint32_t carry = mr >> 3;
    uint32_t mant_norm = carry ? 0u : (mr & 7u);
    int exp_norm = (int)exp - 120 + (int)carry;

    // ---- subnormal path (117 <= exp <= 120): shift 1.mant right, RNE ----
    uint32_t full = (1u << 23) | mant;
    int sh = 141 - (int)exp;
    sh = sh < 1 ? 1 : (sh > 24 ? 24 : sh);
    uint32_t kept_s = full >> sh;
    uint32_t Rs = (full >> (sh - 1)) & 1u;
    uint32_t Ss = (full & ((1u << (sh - 1)) - 1u)) ? 1u : 0u;
    uint32_t Ls = kept_s & 1u;
    uint32_t ms = kept_s + (Rs & (Ss | Ls));
    uint32_t sub_exp  = (ms >= 8u) ? 1u : 0u;
    uint32_t sub_mant = (ms >= 8u) ? 0u : ms;

    // ---- select overflow / subnormal / underflow / normal ----
    uint32_t exp8, mant8;
    if (exp > 134u) {
        exp8 = 15u; mant8 = 6u;
    } else if (exp >= 117u) {
        if (exp <= 120u) { exp8 = sub_exp; mant8 = sub_mant; }
        else             { exp8 = (uint32_t)exp_norm; mant8 = mant_norm; }
    } else {
        exp8 = 0u; mant8 = 0u;         // underflow
    }

    // ---- emit 8 bit-pulses: [S, E3..E0, M2..M0] ----
    float4 o0 = make_float4((float)s,
                            (float)((exp8 >> 3) & 1u),
                            (float)((exp8 >> 2) & 1u),
                            (float)((exp8 >> 1) & 1u));
    float4 o1 = make_float4((float)(exp8 & 1u),
                            (float)((mant8 >> 2) & 1u),
                            (float)((mant8 >> 1) & 1u),
                            (float)(mant8 & 1u));

    float4* op = reinterpret_cast<float4*>(out + (size_t)(base + lane) * 8);
    __stcs(&op[0], o0);    // streaming store
    __stcs(&op[1], o1);

}

extern "C" void kernel_launch(void* const* d_in, const int* in_sizes, int n_in,
                              void* d_out, int out_size)
{
    const float* in  = (const float*)d_in[0];
    float*       out = (float*)d_out;
    const int nvals  = in_sizes[0] / 32;       // 2,097,152

    const int threads = 256;                   // 8 warps -> 256 values per block
    const int blocks = (nvals + threads - 1) / threads;

    fp32_to_fp8_pulse_kernel<<<blocks, threads>>>(in, out, nvals);
}